// round 15
// baseline (speedup 1.0000x reference)
#include <cuda_runtime.h>
#include <cuda_fp16.h>
#include <cstdint>

#define B_SZ 64
#define NS   16
#define SD   256
#define FS   4096

// scratch: S = slots@W1 (1MB), P = pos@W1 + b1 (4MB), W2 fragment-packed (128KB)
static __device__ float    g_S[B_SZ * NS * SD];
static __device__ float    g_P[FS * SD];
static __device__ uint32_t g_W2f[32 * 16 * 32 * 2];   // [ni][kt16][lane][2]

__device__ __forceinline__ void mma_f16(float* c, const uint32_t* a, uint32_t b0, uint32_t b1) {
    asm volatile(
        "mma.sync.aligned.m16n8k16.row.col.f32.f16.f16.f32 "
        "{%0,%1,%2,%3}, {%4,%5,%6,%7}, {%8,%9}, {%0,%1,%2,%3};"
        : "+f"(c[0]), "+f"(c[1]), "+f"(c[2]), "+f"(c[3])
        : "r"(a[0]), "r"(a[1]), "r"(a[2]), "r"(a[3]), "r"(b0), "r"(b1));
}

// ---------------------------------------------------------------------------
// K2: S = slots@W1 ; P = pos@W1 + b1  (fp32 exact, 64x64 tiles)
// ---------------------------------------------------------------------------
__global__ void __launch_bounds__(256) k_pre(const float* __restrict__ slots,
                                             const float* __restrict__ pos,
                                             const float* __restrict__ W1,
                                             const float* __restrict__ b1) {
    __shared__ float As[16][68];
    __shared__ float Bs[16][68];
    const int tid = threadIdx.x;
    const int m0 = blockIdx.x * 64, n0 = blockIdx.y * 64;
    const int tx = tid & 15, ty = tid >> 4;
    const int lm = tid >> 2, kq = tid & 3;
    const int bk = tid >> 4, bn = tid & 15;
    const int rm = m0 + lm;
    const float* arow = (rm < 1024) ? (slots + (size_t)rm * SD)
                                    : (pos + (size_t)(rm - 1024) * SD);
    float acc[4][4] = {};
    for (int kc = 0; kc < 16; kc++) {
        const int k0 = kc * 16;
        float4 av = *(const float4*)(arow + k0 + kq * 4);
        float4 bv = *(const float4*)(W1 + (size_t)(k0 + bk) * SD + n0 + bn * 4);
        __syncthreads();
        As[kq * 4 + 0][lm] = av.x; As[kq * 4 + 1][lm] = av.y;
        As[kq * 4 + 2][lm] = av.z; As[kq * 4 + 3][lm] = av.w;
        *(float4*)&Bs[bk][bn * 4] = bv;
        __syncthreads();
#pragma unroll
        for (int kk = 0; kk < 16; kk++) {
            float4 a4 = *(const float4*)&As[kk][ty * 4];
            float4 b4 = *(const float4*)&Bs[kk][tx * 4];
            float aa[4] = {a4.x, a4.y, a4.z, a4.w};
            float bb[4] = {b4.x, b4.y, b4.z, b4.w};
#pragma unroll
            for (int i = 0; i < 4; i++)
#pragma unroll
                for (int j = 0; j < 4; j++) acc[i][j] += aa[i] * bb[j];
        }
    }
    float4 b1v = *(const float4*)(b1 + n0 + tx * 4);
    float badd[4] = {b1v.x, b1v.y, b1v.z, b1v.w};
#pragma unroll
    for (int i = 0; i < 4; i++) {
        int m = m0 + ty * 4 + i;
        if (m < 1024) {
            *(float4*)(g_S + (size_t)m * SD + n0 + tx * 4) =
                make_float4(acc[i][0], acc[i][1], acc[i][2], acc[i][3]);
        } else {
            *(float4*)(g_P + (size_t)(m - 1024) * SD + n0 + tx * 4) =
                make_float4(acc[i][0] + badd[0], acc[i][1] + badd[1],
                            acc[i][2] + badd[2], acc[i][3] + badd[3]);
        }
    }
}

// ---------------------------------------------------------------------------
// K2b: pack W2 [K,N] into half fragments g_W2f[ni][kt16][lane][2]
//   b0 = (W2[k, n], W2[k+1, n]), b1 = (W2[k+8, n], W2[k+9, n])
//   with n = ni*8 + lane/4, k = kt16*16 + (lane%4)*2
// ---------------------------------------------------------------------------
__global__ void __launch_bounds__(256) k_w2f(const float* __restrict__ W2) {
    int t = blockIdx.x * 256 + threadIdx.x;     // 16384 tasks
    int lane = t & 31, kt = (t >> 5) & 15, ni = t >> 9;
    int n = ni * 8 + (lane >> 2);
    int k = kt * 16 + (lane & 3) * 2;
    __half2 b0 = __floats2half2_rn(W2[(size_t)k * SD + n], W2[(size_t)(k + 1) * SD + n]);
    __half2 b1 = __floats2half2_rn(W2[(size_t)(k + 8) * SD + n], W2[(size_t)(k + 9) * SD + n]);
    g_W2f[t * 2 + 0] = *(uint32_t*)&b0;
    g_W2f[t * 2 + 1] = *(uint32_t*)&b1;
}

// ---------------------------------------------------------------------------
// K3: fused argmax + gather + ReLU + GEMM2, fp16 mma.sync m16n8k16, fp32 acc.
// CTA = 128(M=f) x 256(N full), 256 threads = 8 warps (2 wm x 4 wn),
// warp tile 64x64. Argmax computed in-CTA (idx is CTA-private). Whole-K A
// tile built once in fragment order; mma loop is sync-free and software-
// pipelined: register double-buffer for A (LDS) and B (LDG, L1-resident).
// ---------------------------------------------------------------------------
#define ASTRIDE 34                       // words per fragment (32 lanes + pad)
#define A_WORDS (8 * 16 * 4 * ASTRIDE)   // 17408 words = 69632 B
#define SMEM_BYTES (A_WORDS * 4 + 128 * 4 + 256 * 4)

__global__ void __launch_bounds__(256, 1) k_main(const float* __restrict__ mask,
                                                 const float* __restrict__ b2,
                                                 float* __restrict__ out) {
    extern __shared__ uint32_t sm[];
    uint32_t* Asm   = sm;
    int*      idx_s = (int*)(sm + A_WORDS);
    float*    b2_s  = (float*)(idx_s + 128);

    const int tid  = threadIdx.x;
    const int lane = tid & 31, wid = tid >> 5;
    const int wm = wid & 1, wn = wid >> 1;          // 2 x 4 warp grid
    const int ft = blockIdx.x, b = blockIdx.y;
    const int f0 = ft * 128;

    // --- in-CTA argmax over the slot axis for this CTA's 128 f-rows ---
    if (tid < 128) {
        const float* mp = mask + (size_t)b * NS * FS + f0 + tid;
        float best = mp[0];
        int bi = 0;
#pragma unroll
        for (int s = 1; s < NS; s++) {
            float v = mp[(size_t)s * FS];
            if (v > best) { best = v; bi = s; }
        }
        idx_s[tid] = bi;
    }
    b2_s[tid] = b2[tid];                            // 256 threads = 256 cols
    __syncthreads();

    const float* Sb = g_S + (size_t)b * NS * SD;

    // --- build A tile (whole K) in fragment order: 4096 octs, 16/thread ---
#pragma unroll 2
    for (int it = 0; it < 16; it++) {
        int t = it * 256 + tid;
        int r = t >> 5, au = t & 31;
        const float* pP = g_P + (size_t)(f0 + r) * SD + au * 8;
        const float* pS = Sb + (size_t)idx_s[r] * SD + au * 8;
        float4 p0 = *(const float4*)(pP);
        float4 p1 = *(const float4*)(pP + 4);
        float4 s0 = *(const float4*)(pS);
        float4 s1 = *(const float4*)(pS + 4);
        __half2 h0 = __floats2half2_rn(fmaxf(p0.x + s0.x, 0.f), fmaxf(p0.y + s0.y, 0.f));
        __half2 h1 = __floats2half2_rn(fmaxf(p0.z + s0.z, 0.f), fmaxf(p0.w + s0.w, 0.f));
        __half2 h2 = __floats2half2_rn(fmaxf(p1.x + s1.x, 0.f), fmaxf(p1.y + s1.y, 0.f));
        __half2 h3 = __floats2half2_rn(fmaxf(p1.z + s1.z, 0.f), fmaxf(p1.w + s1.w, 0.f));
        int ks16 = au >> 1, kbit = au & 1;
        int arr = r & 15, mi = r >> 4, ag = arr & 7, ahi = arr >> 3;
        int reg = ahi + 2 * kbit;
        uint32_t base = (uint32_t)(((mi * 16 + ks16) * 4 + reg) * ASTRIDE + ag * 4);
        *(uint2*)&Asm[base + 0] = make_uint2(*(uint32_t*)&h0, *(uint32_t*)&h1);
        *(uint2*)&Asm[base + 2] = make_uint2(*(uint32_t*)&h2, *(uint32_t*)&h3);
    }
    __syncthreads();

    // --- accumulators: warp tile 64(m) x 64(n) ---
    float c[4][8][4];
#pragma unroll
    for (int m = 0; m < 4; m++)
#pragma unroll
        for (int n = 0; n < 8; n++)
#pragma unroll
            for (int k = 0; k < 4; k++) c[m][n][k] = 0.f;

    const uint32_t* Bf = g_W2f + ((size_t)(wn * 8) * 16 * 64) + lane * 2;
    const uint32_t* Aw = Asm + (wm * 4) * 16 * 4 * ASTRIDE + lane;

    // --- software-pipelined mma loop: register double-buffer A and B ---
    uint32_t a[2][4][4];
    uint2    bb[2][8];
#pragma unroll
    for (int m = 0; m < 4; m++)
#pragma unroll
        for (int rg = 0; rg < 4; rg++)
            a[0][m][rg] = Aw[((m * 16 + 0) * 4 + rg) * ASTRIDE];
#pragma unroll
    for (int nf = 0; nf < 8; nf++)
        bb[0][nf] = *(const uint2*)(Bf + nf * 1024);

#pragma unroll 2
    for (int kt = 0; kt < 16; kt++) {
        const int cur = kt & 1, nxt = cur ^ 1;
        if (kt < 15) {
            // prefetch stage kt+1 (retires under the mma block below)
#pragma unroll
            for (int m = 0; m < 4; m++)
#pragma unroll
                for (int rg = 0; rg < 4; rg++)
                    a[nxt][m][rg] = Aw[((m * 16 + kt + 1) * 4 + rg) * ASTRIDE];
            const uint32_t* Bk = Bf + (kt + 1) * 64;
#pragma unroll
            for (int nf = 0; nf < 8; nf++)
                bb[nxt][nf] = *(const uint2*)(Bk + nf * 1024);
        }
#pragma unroll
        for (int nf = 0; nf < 8; nf++) {
            mma_f16(c[0][nf], a[cur][0], bb[cur][nf].x, bb[cur][nf].y);
            mma_f16(c[1][nf], a[cur][1], bb[cur][nf].x, bb[cur][nf].y);
            mma_f16(c[2][nf], a[cur][2], bb[cur][nf].x, bb[cur][nf].y);
            mma_f16(c[3][nf], a[cur][3], bb[cur][nf].x, bb[cur][nf].y);
        }
    }

    // --- epilogue: add b2, store fp32 (float2 = full sectors) ---
    const int g = lane >> 2, cc = (lane & 3) * 2;
#pragma unroll
    for (int m = 0; m < 4; m++) {
        int rbase = f0 + wm * 64 + m * 16 + g;
#pragma unroll
        for (int nf = 0; nf < 8; nf++) {
            int coll = wn * 64 + nf * 8 + cc;
            float bx = b2_s[coll], by = b2_s[coll + 1];
            size_t o0 = ((size_t)(b * FS + rbase)) * SD + coll;
            size_t o1 = ((size_t)(b * FS + rbase + 8)) * SD + coll;
            *(float2*)(out + o0) = make_float2(c[m][nf][0] + bx, c[m][nf][1] + by);
            *(float2*)(out + o1) = make_float2(c[m][nf][2] + bx, c[m][nf][3] + by);
        }
    }
}

// ---------------------------------------------------------------------------
extern "C" void kernel_launch(void* const* d_in, const int* in_sizes, int n_in,
                              void* d_out, int out_size) {
    const float* slots = (const float*)d_in[0];
    const float* mask  = (const float*)d_in[1];
    const float* pos   = (const float*)d_in[2];
    const float* W1    = (const float*)d_in[3];
    const float* b1    = (const float*)d_in[4];
    const float* W2    = (const float*)d_in[5];
    const float* b2    = (const float*)d_in[6];
    float* out = (float*)d_out;

    cudaFuncSetAttribute(k_main, cudaFuncAttributeMaxDynamicSharedMemorySize, SMEM_BYTES);

    k_pre<<<dim3(80, 4), 256>>>(slots, pos, W1, b1);
    k_w2f<<<64, 256>>>(W2);
    k_main<<<dim3(32, 64), 256, SMEM_BYTES>>>(mask, b2, out);
}